// round 14
// baseline (speedup 1.0000x reference)
#include <cuda_runtime.h>
#include <cuda_fp16.h>
#include <math.h>
#include <stdint.h>

#define B_   16
#define G_   2048
#define D_   256
#define H_   8
#define DH_  32
#define FFN_ 1024
#define L_   4
#define CH_  64
#define NC_  (G_ / CH_)           // 32 chunks
#define BG_  (B_ * G_)            // 32768 rows
#define BH_  (B_ * H_)            // 128

// ---------------- scratch (device globals; no runtime allocation) ----------
__device__ float  g_h[(size_t)BG_ * D_];
__device__ __half g_hn[(size_t)BG_ * D_];
__device__ __half g_q[(size_t)BG_ * D_];
__device__ __half g_k[(size_t)BG_ * D_];
__device__ __half g_v[(size_t)BG_ * D_];
__device__ __half g_mid[(size_t)BG_ * FFN_];
__device__ float  g_ckv[(size_t)BH_ * NC_ * DH_ * DH_];
__device__ float  g_cks[(size_t)BH_ * NC_ * DH_];
// fp16 [N,K] K-major transposed weights
__device__ __half g_WqT[(size_t)L_ * D_ * D_];
__device__ __half g_WkT[(size_t)L_ * D_ * D_];
__device__ __half g_WvT[(size_t)L_ * D_ * D_];
__device__ __half g_WUT[(size_t)L_ * D_ * FFN_];
__device__ __half g_WVT[(size_t)L_ * FFN_ * D_];

// ========================= helpers =========================================
__device__ __forceinline__ uint32_t smem_u32(const void* p) {
    uint32_t a;
    asm("{ .reg .u64 t; cvta.to.shared.u64 t, %1; cvt.u32.u64 %0, t; }" : "=r"(a) : "l"(p));
    return a;
}
#define CP_ASYNC16(dst, src) \
    asm volatile("cp.async.cg.shared.global [%0], [%1], 16;" :: "r"(dst), "l"(src))
#define CP_COMMIT() asm volatile("cp.async.commit_group;" ::: "memory")
#define CP_WAIT0()  asm volatile("cp.async.wait_group 0;" ::: "memory")
#define CP_WAIT1()  asm volatile("cp.async.wait_group 1;" ::: "memory")

#define MMA_F16(c, a, b) \
    asm volatile("mma.sync.aligned.m16n8k16.row.col.f32.f16.f16.f32 " \
        "{%0,%1,%2,%3}, {%4,%5,%6,%7}, {%8,%9}, {%0,%1,%2,%3};" \
        : "+f"((c)[0]), "+f"((c)[1]), "+f"((c)[2]), "+f"((c)[3]) \
        : "r"((a)[0]), "r"((a)[1]), "r"((a)[2]), "r"((a)[3]), \
          "r"((b)[0]), "r"((b)[1]))

#define LDMX4(r0, r1, r2, r3, addr) \
    asm volatile("ldmatrix.sync.aligned.m8n8.x4.shared.b16 {%0,%1,%2,%3}, [%4];" \
        : "=r"(r0), "=r"(r1), "=r"(r2), "=r"(r3) : "r"(addr))

// ========================= fp16 mma.sync GEMM ==============================
// CTA tile 128x128, K-tile 64, 8 warps (4m x 2n), warp tile 32x64.
// 3-stage cp.async pipeline -> 110.6 KB smem -> 2 CTAs/SM.
// Fragments double-buffered across kk (software pipeline).
#define LDH_    72
#define ATILEH_ (128 * LDH_)               // halves
#define BTILEH_ (128 * LDH_)
#define STGB_   ((ATILEH_ + BTILEH_) * 2)  // 36864 bytes per stage
#define NSTG_   3
#define GSMEM_  (NSTG_ * STGB_)            // 110592 bytes

__device__ __forceinline__ void g_load_tile(const __half* __restrict__ A,
                                            const __half* __restrict__ Bt,
                                            int m0, int n0, int K, int kt,
                                            uint32_t su, int stage, int tid) {
    const __half* Ag = A  + (size_t)m0 * K + kt * 64;
    const __half* Bg = Bt + (size_t)n0 * K + kt * 64;
    uint32_t as = su + stage * STGB_;
    uint32_t bs = as + ATILEH_ * 2;
#pragma unroll
    for (int i = 0; i < 4; i++) {
        int c = tid + (i << 8);
        int row = c >> 3, c8 = c & 7;
        CP_ASYNC16(as + row * (LDH_ * 2) + (c8 << 4),
                   Ag + (size_t)row * K + (c8 << 3));
    }
#pragma unroll
    for (int i = 0; i < 4; i++) {
        int c = tid + (i << 8);
        int row = c >> 3, c8 = c & 7;
        CP_ASYNC16(bs + row * (LDH_ * 2) + (c8 << 4),
                   Bg + (size_t)row * K + (c8 << 3));
    }
    CP_COMMIT();
}

#define LDFRAG(buf, koff_)                                                       \
    do {                                                                         \
        _Pragma("unroll")                                                        \
        for (int mt = 0; mt < 2; mt++)                                           \
            LDMX4(a[buf][mt][0], a[buf][mt][1], a[buf][mt][2], a[buf][mt][3],    \
                  sbase + a_loff + (koff_) + mt * (16 * LDH_ * 2));              \
        _Pragma("unroll")                                                        \
        for (int p = 0; p < 4; p++)                                              \
            LDMX4(b[buf][2 * p][0], b[buf][2 * p][1],                            \
                  b[buf][2 * p + 1][0], b[buf][2 * p + 1][1],                    \
                  sbase + b_loff + (koff_) + p * (16 * LDH_ * 2));               \
    } while (0)

#define GEMM_MAINLOOP(A_, B_ptr_, K_)                                            \
    const int T = (K_) / 64;                                                     \
    const uint32_t a_loff = (wm + ((lane >> 3) & 1) * 8 + (lane & 7)) *          \
                            (LDH_ * 2) + (lane >> 4) * 16;                       \
    const uint32_t b_loff = ATILEH_ * 2 +                                        \
                            (wn + ((lane >> 4) & 1) * 8 + (lane & 7)) *          \
                            (LDH_ * 2) + ((lane >> 3) & 1) * 16;                 \
    g_load_tile(A_, B_ptr_, m0, n0, K_, 0, su, 0, tid);                          \
    if (T > 1) g_load_tile(A_, B_ptr_, m0, n0, K_, 1, su, 1, tid);               \
    for (int kt = 0; kt < T; kt++) {                                             \
        if (kt + 2 <= T) CP_WAIT1(); else CP_WAIT0();                            \
        __syncthreads();                                                         \
        if (kt + 2 < T)                                                          \
            g_load_tile(A_, B_ptr_, m0, n0, K_, kt + 2, su, (kt + 2) % NSTG_, tid); \
        uint32_t sbase = su + (kt % NSTG_) * STGB_;                              \
        uint32_t a[2][2][4], b[2][8][2];                                         \
        LDFRAG(0, 0);                                                            \
        _Pragma("unroll")                                                        \
        for (int kk = 0; kk < 4; kk++) {                                         \
            if (kk < 3) LDFRAG((kk + 1) & 1, (kk + 1) * 32);                     \
            _Pragma("unroll")                                                    \
            for (int mt = 0; mt < 2; mt++)                                       \
                _Pragma("unroll")                                                \
                for (int nt = 0; nt < 8; nt++)                                   \
                    MMA_F16(acc[mt][nt], a[kk & 1][mt], b[kk & 1][nt]);          \
        }                                                                        \
    }

// FFN1: gelu(x+bias) -> fp16 mid
__global__ __launch_bounds__(256, 2)
void ffn1_gemm(const __half* __restrict__ A, const __half* __restrict__ Bt,
               const float* __restrict__ bias, __half* __restrict__ Ch,
               int M, int N, int K) {
    extern __shared__ float sm[];
    uint32_t su = smem_u32(sm);
    const int tid = threadIdx.x, lane = tid & 31, warp = tid >> 5;
    const int m0 = blockIdx.y * 128, n0 = blockIdx.x * 128;
    const int wm = (warp >> 1) * 32, wn = (warp & 1) * 64;
    const int lg = lane >> 2, l4 = lane & 3;

    float acc[2][8][4];
#pragma unroll
    for (int mt = 0; mt < 2; mt++)
#pragma unroll
        for (int nt = 0; nt < 8; nt++)
#pragma unroll
            for (int e = 0; e < 4; e++) acc[mt][nt][e] = 0.f;

    GEMM_MAINLOOP(A, Bt, K)

#pragma unroll
    for (int mt = 0; mt < 2; mt++) {
#pragma unroll
        for (int nt = 0; nt < 8; nt++) {
            int row = m0 + wm + mt * 16 + lg;
            int col = n0 + wn + nt * 8 + l4 * 2;
            float b0 = __ldg(bias + col), b1 = __ldg(bias + col + 1);
#pragma unroll
            for (int half_ = 0; half_ < 2; half_++) {
                int r = row + half_ * 8;
                float v0 = acc[mt][nt][half_ * 2 + 0] + b0;
                float v1 = acc[mt][nt][half_ * 2 + 1] + b1;
                v0 = 0.5f * v0 * (1.0f + erff(v0 * 0.70710678118654752f));
                v1 = 0.5f * v1 * (1.0f + erff(v1 * 0.70710678118654752f));
                *(half2*)(Ch + (size_t)r * N + col) = __floats2half2_rn(v0, v1);
            }
        }
    }
}

// FFN2: h += x + bias  (fp32 accumulate into residual)
__global__ __launch_bounds__(256, 2)
void ffn2_gemm(const __half* __restrict__ A, const __half* __restrict__ Bt,
               const float* __restrict__ bias, float* __restrict__ C,
               int M, int N, int K) {
    extern __shared__ float sm[];
    uint32_t su = smem_u32(sm);
    const int tid = threadIdx.x, lane = tid & 31, warp = tid >> 5;
    const int m0 = blockIdx.y * 128, n0 = blockIdx.x * 128;
    const int wm = (warp >> 1) * 32, wn = (warp & 1) * 64;
    const int lg = lane >> 2, l4 = lane & 3;

    float acc[2][8][4];
#pragma unroll
    for (int mt = 0; mt < 2; mt++)
#pragma unroll
        for (int nt = 0; nt < 8; nt++)
#pragma unroll
            for (int e = 0; e < 4; e++) acc[mt][nt][e] = 0.f;

    GEMM_MAINLOOP(A, Bt, K)

#pragma unroll
    for (int mt = 0; mt < 2; mt++) {
#pragma unroll
        for (int nt = 0; nt < 8; nt++) {
            int row = m0 + wm + mt * 16 + lg;
            int col = n0 + wn + nt * 8 + l4 * 2;
            float b0 = __ldg(bias + col), b1 = __ldg(bias + col + 1);
#pragma unroll
            for (int half_ = 0; half_ < 2; half_++) {
                int r = row + half_ * 8;
                float2* p = (float2*)(C + (size_t)r * N + col);
                float2 o = *p;
                o.x += acc[mt][nt][half_ * 2 + 0] + b0;
                o.y += acc[mt][nt][half_ * 2 + 1] + b1;
                *p = o;
            }
        }
    }
}

// Fused QKV GEMM -> fp16 outputs; square epilogue for q,k.
__global__ __launch_bounds__(256, 2)
void qkv_gemm(const __half* __restrict__ A,
              const __half* __restrict__ WqT, const __half* __restrict__ WkT,
              const __half* __restrict__ WvT,
              const float* __restrict__ bq, const float* __restrict__ bk,
              const float* __restrict__ bv,
              __half* __restrict__ Q, __half* __restrict__ Ko, __half* __restrict__ V) {
    extern __shared__ float sm[];
    uint32_t su = smem_u32(sm);
    const int tid = threadIdx.x, lane = tid & 31, warp = tid >> 5;
    const int which = blockIdx.x >> 1;
    const int m0 = blockIdx.y * 128, n0 = (blockIdx.x & 1) * 128;
    const int wm = (warp >> 1) * 32, wn = (warp & 1) * 64;
    const int lg = lane >> 2, l4 = lane & 3;
    const int N = D_, K = D_;

    const __half* Bt  = (which == 0) ? WqT : (which == 1) ? WkT : WvT;
    const float* bias = (which == 0) ? bq : (which == 1) ? bk : bv;
    __half* C = (which == 0) ? Q : (which == 1) ? Ko : V;
    const bool sq = (which < 2);

    float acc[2][8][4];
#pragma unroll
    for (int mt = 0; mt < 2; mt++)
#pragma unroll
        for (int nt = 0; nt < 8; nt++)
#pragma unroll
            for (int e = 0; e < 4; e++) acc[mt][nt][e] = 0.f;

    GEMM_MAINLOOP(A, Bt, K)

#pragma unroll
    for (int mt = 0; mt < 2; mt++) {
#pragma unroll
        for (int nt = 0; nt < 8; nt++) {
            int row = m0 + wm + mt * 16 + lg;
            int col = n0 + wn + nt * 8 + l4 * 2;
            float b0 = __ldg(bias + col), b1 = __ldg(bias + col + 1);
#pragma unroll
            for (int half_ = 0; half_ < 2; half_++) {
                int r = row + half_ * 8;
                float v0 = acc[mt][nt][half_ * 2 + 0] + b0;
                float v1 = acc[mt][nt][half_ * 2 + 1] + b1;
                if (sq) { v0 = v0 * v0; v1 = v1 * v1; }
                *(half2*)(C + (size_t)r * N + col) = __floats2half2_rn(v0, v1);
            }
        }
    }
}

// -------- weight transpose+convert: out[n*K+k] = fp16(in[k*N+n]) ------------
__global__ void transconv_kernel(const float* __restrict__ in, __half* __restrict__ out,
                                 int Kdim, int Ndim) {
    __shared__ float t[32][33];
    size_t off = (size_t)blockIdx.z * Kdim * Ndim;
    int k0 = blockIdx.y * 32, n0 = blockIdx.x * 32;
    int tx = threadIdx.x, ty = threadIdx.y;   // 32 x 8
#pragma unroll
    for (int i = ty; i < 32; i += 8)
        t[i][tx] = in[off + (size_t)(k0 + i) * Ndim + n0 + tx];
    __syncthreads();
#pragma unroll
    for (int i = ty; i < 32; i += 8)
        out[off + (size_t)(n0 + i) * Kdim + k0 + tx] = __float2half_rn(t[tx][i]);
}

// half8 -> 8 floats
__device__ __forceinline__ void h8_to_f8(uint4 raw, float* f) {
    half2* hp = (half2*)&raw;
#pragma unroll
    for (int i = 0; i < 4; i++) {
        float2 fv = __half22float2(hp[i]);
        f[2 * i] = fv.x; f[2 * i + 1] = fv.y;
    }
}

// ========= attention phase 1: per-chunk K^T V and sum(k) (fp16 in) =========
__global__ __launch_bounds__(256)
void attn_p1(const __half* __restrict__ k, const __half* __restrict__ v,
             float* __restrict__ ckv, float* __restrict__ cks) {
    __shared__ float Ks[CH_][36], Vs[CH_][36];
    int blk = blockIdx.x;
    int c = blk & (NC_ - 1);
    int bh = blk >> 5;
    int b = bh >> 3, hh = bh & 7;
    int t = threadIdx.x;
    size_t base = ((size_t)(b * G_ + c * CH_)) * D_ + hh * DH_;

    {
        int row = t >> 2, c8 = (t & 3) * 8;
        size_t gi = base + (size_t)row * D_ + c8;
        float kf[8], vf[8];
        h8_to_f8(*(const uint4*)(k + gi), kf);
        h8_to_f8(*(const uint4*)(v + gi), vf);
#pragma unroll
        for (int i = 0; i < 8; i++) { Ks[row][c8 + i] = kf[i]; Vs[row][c8 + i] = vf[i]; }
    }
    __syncthreads();

    int f = t >> 4, d0 = (t & 15) * 2;
    float a00 = 0.f, a01 = 0.f, a10 = 0.f, a11 = 0.f;
#pragma unroll
    for (int i = 0; i < CH_; i++) {
        float k0v = Ks[i][f];
        float k1v = Ks[i][f + 16];
        float2 vv = *(float2*)&Vs[i][d0];
        a00 = fmaf(k0v, vv.x, a00); a01 = fmaf(k0v, vv.y, a01);
        a10 = fmaf(k1v, vv.x, a10); a11 = fmaf(k1v, vv.y, a11);
    }
    float* cbase = ckv + (size_t)blk * (DH_ * DH_);
    *(float2*)(cbase + f * DH_ + d0)        = make_float2(a00, a01);
    *(float2*)(cbase + (f + 16) * DH_ + d0) = make_float2(a10, a11);

    if (t < DH_) {
        float s = 0.f;
#pragma unroll
        for (int i = 0; i < CH_; i++) s += Ks[i][t];
        cks[(size_t)blk * DH_ + t] = s;
    }
}

// ========= attention phase 2: exclusive prefix across chunks ===============
__global__ void attn_p2(float* __restrict__ ckv, float* __restrict__ cks) {
    int bh = blockIdx.x;
    int t = threadIdx.x;   // 1024 threads
    float run = 0.f;
    for (int c = 0; c < NC_; c++) {
        size_t idx = ((size_t)(bh * NC_ + c)) * (DH_ * DH_) + t;
        float tmp = ckv[idx];
        ckv[idx] = run;
        run += tmp;
    }
    if (t < DH_) {
        float r2 = 0.f;
        for (int c = 0; c < NC_; c++) {
            size_t idx = ((size_t)(bh * NC_ + c)) * DH_ + t;
            float tmp = cks[idx];
            cks[idx] = r2;
            r2 += tmp;
        }
    }
}

// ========= attention phase 3: output + residual, paired rows ===============
__global__ __launch_bounds__(256)
void attn_p3(const __half* __restrict__ q, const __half* __restrict__ k,
             const __half* __restrict__ v,
             const float* __restrict__ ckv, const float* __restrict__ cks,
             float* __restrict__ h) {
    __shared__ float Qs[CH_][36];
    __shared__ float Vs[CH_][36];
    __shared__ float Kt[DH_][68];
    __shared__ float As[CH_][66];
    __shared__ float Ss[DH_][36];
    __shared__ float den[CH_], zz[DH_];

    int blk = blockIdx.x;
    int c = blk & (NC_ - 1);
    int bh = blk >> 5;
    int b = bh >> 3, hh = bh & 7;
    int t = threadIdx.x;
    size_t base = ((size_t)(b * G_ + c * CH_)) * D_ + hh * DH_;

    {
        int row = t >> 2, c8 = (t & 3) * 8;
        size_t gi = base + (size_t)row * D_ + c8;
        float qf[8], kf[8], vf[8];
        h8_to_f8(*(const uint4*)(q + gi), qf);
        h8_to_f8(*(const uint4*)(k + gi), kf);
        h8_to_f8(*(const uint4*)(v + gi), vf);
#pragma unroll
        for (int i = 0; i < 8; i++) {
            Qs[row][c8 + i] = qf[i];
            Vs[row][c8 + i] = vf[i];
            Kt[c8 + i][row] = kf[i];
        }
    }
#pragma unroll
    for (int it = 0; it < 4; it++) {
        int e = t + it * 256;
        Ss[e >> 5][e & 31] = ckv[(size_t)blk * (DH_ * DH_) + e];
    }
    if (t < DH_) zz[t] = cks[(size_t)blk * DH_ + t];
    __syncthreads();

    {
        int i0 = (t >> 4) * 4, j0 = (t & 15) * 4;
        float a4[4][4];
#pragma unroll
        for (int r = 0; r < 4; r++)
#pragma unroll
            for (int cc = 0; cc < 4; cc++) a4[r][cc] = 0.f;
#pragma unroll
        for (int f = 0; f < DH_; f++) {
            float qr[4];
#pragma unroll
            for (int r = 0; r < 4; r++) qr[r] = Qs[i0 + r][f];
            float4 kk = *(float4*)&Kt[f][j0];
#pragma unroll
            for (int r = 0; r < 4; r++) {
                a4[r][0] = fmaf(qr[r], kk.x, a4[r][0]);
                a4[r][1] = fmaf(qr[r], kk.y, a4[r][1]);
                a4[r][2] = fmaf(qr[r], kk.z, a4[r][2]);
                a4[r][3] = fmaf(qr[r], kk.w, a4[r][3]);
            }
        }
#pragma unroll
        for (int r = 0; r < 4; r++)
#pragma unroll
            for (int cc = 0; cc < 4; cc++) As[i0 + r][j0 + cc] = a4[r][cc];
    }
    __syncthreads();

    {
        int i = t >> 2, r = t & 3;
        float s = 0.f;
        for (int f = r; f < DH_; f += 4) s = fmaf(Qs[i][f], zz[f], s);
        for (int j = r; j <= i; j += 4) s += As[i][j];
        s += __shfl_xor_sync(0xffffffffu, s, 1);
        s += __shfl_xor_sync(0xffffffffu, s, 2);
        if (r == 0) den[i] = s;
    }
    __syncthreads();

    {
        int i1 = t >> 3, i2 = i1 + 32;
        int d0 = (t & 7) * 4;
        float o10 = 0.f, o11 = 0.f, o12 = 0.f, o13 = 0.f;
        float o20 = 0.f, o21 = 0.f, o22 = 0.f, o23 = 0.f;
#pragma unroll
        for (int f = 0; f < DH_; f++) {
            float4 ss = *(float4*)&Ss[f][d0];
            float q1 = Qs[i1][f], q2 = Qs[i2][f];
            o10 = fmaf(q1, ss.x, o10); o11 = fmaf(q1, ss.y, o11);
            o12 = fmaf(q1, ss.z, o12); o13 = fmaf(q1, ss.w, o13);
            o20 = fmaf(q2, ss.x, o20); o21 = fmaf(q2, ss.y, o21);
            o22 = fmaf(q2, ss.z, o22); o23 = fmaf(q2, ss.w, o23);
        }
        for (int j = 0; j <= i1; j++) {
            float4 vv = *(float4*)&Vs[j][d0];
            float a1 = As[i1][j], a2 = As[i2][j];
            o10 = fmaf(a1, vv.x, o10); o11 = fmaf(a1, vv.y, o11);
            o12 = fmaf(a1, vv.z, o12); o13 = fmaf(a1, vv.w, o13);
            o20 = fmaf(a2, vv.x, o20); o21 = fmaf(a2, vv.y, o21);
            o22 = fmaf(a2, vv.z, o22); o23 = fmaf(a2, vv.w, o23);
        }
        for (int j = i1 + 1; j <= i2; j++) {
            float4 vv = *(float4*)&Vs[j][d0];
            float a2 = As[i2][j];
            o20 = fmaf(a2, vv.x, o20); o21 = fmaf(a2, vv.y, o21);
            o22 = fmaf(a2, vv.z, o22); o23 = fmaf(a2, vv.w, o23);
        }
        float inv1 = 1.0f / (den[i1] + 1e-16f);
        float inv2 = 1.0f / (den[i2] + 1e-16f);
        float4* p1 = (float4*)(h + base + (size_t)i1 * D_ + d0);
        float4 hv1 = *p1;
        hv1.x += o10 * inv1; hv1.y += o11 * inv1;
        hv1.z += o12 * inv1; hv1.w += o13 * inv1;
        *p1 = hv1;
        float4* p2 = (float4*)(h + base + (size_t)i2 * D_ + d0);
        float4 hv2 = *p2;
        hv2.x += o20 * inv2; hv2.y += o21 * inv2;
        hv2.z += o22 * inv2; hv2.w += o23 * inv2;
        *p2 = hv2;
    }
}

// ---------------- embedding: h = gene_emb + REE(x) -------------------------
__global__ void embed_kernel(const float* __restrict__ x,
                             const float* __restrict__ ge,
                             const float* __restrict__ invf,
                             float* __restrict__ h) {
    size_t idx = (size_t)blockIdx.x * 256 + threadIdx.x;
    int d = (int)(idx & (D_ - 1));
    size_t bg = idx >> 8;
    int g = (int)(bg & (G_ - 1));
    float xv = x[bg];
    float e;
    if (d < D_ / 2) e = sinf(xv * invf[d]);
    else            e = cosf(xv * invf[d - D_ / 2]);
    if (xv == -10.0f) e = 0.0f;
    h[idx] = ge[(size_t)g * D_ + d] + e;
}

// ---------------- layernorm -> fp16 (warp per row, D=256) -------------------
__global__ void ln_kernel(const float* __restrict__ x,
                          const float* __restrict__ gam,
                          const float* __restrict__ bet,
                          __half* __restrict__ out) {
    int warp = threadIdx.x >> 5, lane = threadIdx.x & 31;
    int row = blockIdx.x * 8 + warp;
    const float* xr = x + (size_t)row * D_;
    float vals[8];
    float s = 0.f;
#pragma unroll
    for (int i = 0; i < 8; i++) { vals[i] = xr[lane + i * 32]; s += vals[i]; }
#pragma unroll
    for (int o = 16; o; o >>= 1) s += __shfl_xor_sync(0xffffffffu, s, o);
    float mean = s * (1.0f / D_);
    float vs = 0.f;
#pragma unroll
    for (int i = 0; i < 8; i++) { float dlt = vals[i] - mean; vs += dlt * dlt; }
#pragma unroll
    for (int o = 16; o; o >>= 1) vs += __shfl_xor_sync(0xffffffffu, vs, o);
    float rstd = rsqrtf(vs * (1.0f / D_) + 1e-5f);
    __half* orow = out + (size_t)row * D_;
#pragma unroll
    for (int i = 0; i < 8; i++) {
        int c = lane + i * 32;
        orow[c] = __float2half_rn((vals[i] - mean) * rstd * gam[c] + bet[c]);
    }
}

// ---------------- final projection: out = h @ Wout + bout -------------------
__global__ void out_kernel(const float* __restrict__ h, const float* __restrict__ Wout,
                           const float* __restrict__ bout, float* __restrict__ out) {
    int warp = threadIdx.x >> 5, lane = threadIdx.x & 31;
    int row = blockIdx.x * 8 + warp;
    const float* hr = h + (size_t)row * D_;
    float s = 0.f;
#pragma unroll
    for (int i = 0; i < 8; i++) {
        int c = lane + i * 32;
        s = fmaf(hr[c], Wout[c], s);
    }
#pragma unroll
    for (int o = 16; o; o >>= 1) s += __shfl_xor_sync(0xffffffffu, s, o);
    if (lane == 0) out[row] = s + bout[0];
}

// ---------------------------------------------------------------------------
extern "C" void kernel_launch(void* const* d_in, const int* in_sizes, int n_in,
                              void* d_out, int out_size) {
    const float* x        = (const float*)d_in[0];
    const float* gene_emb = (const float*)d_in[1];
    const float* inv_freq = (const float*)d_in[2];
    const float* Wq       = (const float*)d_in[3];
    const float* bq       = (const float*)d_in[4];
    const float* Wk       = (const float*)d_in[5];
    const float* bk       = (const float*)d_in[6];
    const float* Wv       = (const float*)d_in[7];
    const float* bv       = (const float*)d_in[8];
    const float* ln1_g    = (const float*)d_in[9];
    const float* ln1_b    = (const float*)d_in[10];
    const float* ln2_g    = (const float*)d_in[11];
    const float* ln2_b    = (const float*)d_in[12];
    const float* WU       = (const float*)d_in[13];
    const float* bU       = (const float*)d_in[14];
    const float* WV       = (const float*)d_in[15];
    const float* bV       = (const float*)d_in[16];
    const float* Wout     = (const float*)d_in[17];
    const float* bout     = (const float*)d_in[18];
    float* out = (float*)d_out;

    float *h, *ckv, *cks;
    __half *hn, *q, *k, *v, *mid, *WqT, *WkT, *WvT, *WUT, *WVT;
    cudaGetSymbolAddress((void**)&h,   g_h);
    cudaGetSymbolAddress((void**)&hn,  g_hn);
    cudaGetSymbolAddress((void**)&q,   g_q);
    cudaGetSymbolAddress((void**)&k,   g_k);
    cudaGetSymbolAddress((void**)&v,   g_v);
    cudaGetSymbolAddress((void**)&mid, g_mid);
    cudaGetSymbolAddress((void**)&ckv, g_ckv);
    cudaGetSymbolAddress((void**)&cks, g_cks);
    cudaGetSymbolAddress((void**)&WqT, g_WqT);
    cudaGetSymbolAddress((void**)&WkT, g_WkT);
    cudaGetSymbolAddress((void**)&WvT, g_WvT);
    cudaGetSymbolAddress((void**)&WUT, g_WUT);
    cudaGetSymbolAddress((void**)&WVT, g_WVT);

    cudaFuncSetAttribute(qkv_gemm,  cudaFuncAttributeMaxDynamicSharedMemorySize, GSMEM_);
    cudaFuncSetAttribute(ffn1_gemm, cudaFuncAttributeMaxDynamicSharedMemorySize, GSMEM_);
    cudaFuncSetAttribute(ffn2_gemm, cudaFuncAttributeMaxDynamicSharedMemorySize, GSMEM_);

    // batched transpose+convert (one launch per weight tensor, grid.z = L)
    {
        dim3 tb(32, 8);
        transconv_kernel<<<dim3(D_ / 32, D_ / 32, L_), tb>>>(Wq, WqT, D_, D_);
        transconv_kernel<<<dim3(D_ / 32, D_ / 32, L_), tb>>>(Wk, WkT, D_, D_);
        transconv_kernel<<<dim3(D_ / 32, D_ / 32, L_), tb>>>(Wv, WvT, D_, D_);
        transconv_kernel<<<dim3(FFN_ / 32, D_ / 32, L_), tb>>>(WU, WUT, D_, FFN_);
        transconv_kernel<<<dim3(D_ / 32, FFN_ / 32, L_), tb>>>(WV, WVT, FFN_, D_);
    }

    embed_kernel<<<(BG_ * D_) / 256, 256>>>(x, gene_emb, inv_freq, h);

    for (int l = 0; l < L_; l++) {
        const size_t wOff  = (size_t)l * D_ * D_;
        const size_t bOff  = (size_t)l * D_;
        const size_t uOff  = (size_t)l * D_ * FFN_;
        const size_t ubOff = (size_t)l * FFN_;
        const size_t vOff  = (size_t)l * FFN_ * D_;

        ln_kernel<<<BG_ / 8, 256>>>(h, ln1_g + bOff, ln1_b + bOff, hn);

        qkv_gemm<<<dim3(6, BG_ / 128), 256, GSMEM_>>>(
            hn, WqT + wOff, WkT + wOff, WvT + wOff,
            bq + bOff, bk + bOff, bv + bOff, q, k, v);

        attn_p1<<<BH_ * NC_, 256>>>(k, v, ckv, cks);
        attn_p2<<<BH_, 1024>>>(ckv, cks);
        attn_p3<<<BH_ * NC_, 256>>>(q, k, v, ckv, cks, h);

        ln_kernel<<<BG_ / 8, 256>>>(h, ln2_g + bOff, ln2_b + bOff, hn);

        ffn1_gemm<<<dim3(FFN_ / 128, BG_ / 128), 256, GSMEM_>>>(hn, WUT + uOff, bU + ubOff, mid, BG_, FFN_, D_);
        ffn2_gemm<<<dim3(D_ / 128, BG_ / 128), 256, GSMEM_>>>(mid, WVT + vOff, bV + bOff, h, BG_, D_, FFN_);
    }

    out_kernel<<<BG_ / 8, 256>>>(h, Wout, bout, out);
}

// round 15
// speedup vs baseline: 1.0676x; 1.0676x over previous
#include <cuda_runtime.h>
#include <cuda_fp16.h>
#include <math.h>
#include <stdint.h>

#define B_   16
#define G_   2048
#define D_   256
#define H_   8
#define DH_  32
#define FFN_ 1024
#define L_   4
#define CH_  64
#define NC_  (G_ / CH_)           // 32 chunks
#define BG_  (B_ * G_)            // 32768 rows
#define BH_  (B_ * H_)            // 128

// ---------------- scratch (device globals; no runtime allocation) ----------
__device__ float  g_h[(size_t)BG_ * D_];
__device__ __half g_hn[(size_t)BG_ * D_];
__device__ __half g_q[(size_t)BG_ * D_];
__device__ __half g_k[(size_t)BG_ * D_];
__device__ __half g_v[(size_t)BG_ * D_];
__device__ __half g_mid[(size_t)BG_ * FFN_];
__device__ float  g_ckv[(size_t)BH_ * NC_ * DH_ * DH_];
__device__ float  g_cks[(size_t)BH_ * NC_ * DH_];
// fp16 [N,K] K-major transposed weights
__device__ __half g_WqT[(size_t)L_ * D_ * D_];
__device__ __half g_WkT[(size_t)L_ * D_ * D_];
__device__ __half g_WvT[(size_t)L_ * D_ * D_];
__device__ __half g_WUT[(size_t)L_ * D_ * FFN_];
__device__ __half g_WVT[(size_t)L_ * FFN_ * D_];

// ========================= helpers =========================================
__device__ __forceinline__ uint32_t smem_u32(const void* p) {
    uint32_t a;
    asm("{ .reg .u64 t; cvta.to.shared.u64 t, %1; cvt.u32.u64 %0, t; }" : "=r"(a) : "l"(p));
    return a;
}
#define CP_ASYNC16(dst, src) \
    asm volatile("cp.async.cg.shared.global [%0], [%1], 16;" :: "r"(dst), "l"(src))
#define CP_COMMIT() asm volatile("cp.async.commit_group;" ::: "memory")
#define CP_WAIT0()  asm volatile("cp.async.wait_group 0;" ::: "memory")
#define CP_WAIT1()  asm volatile("cp.async.wait_group 1;" ::: "memory")

#define MMA_F16(c, a, b) \
    asm volatile("mma.sync.aligned.m16n8k16.row.col.f32.f16.f16.f32 " \
        "{%0,%1,%2,%3}, {%4,%5,%6,%7}, {%8,%9}, {%0,%1,%2,%3};" \
        : "+f"((c)[0]), "+f"((c)[1]), "+f"((c)[2]), "+f"((c)[3]) \
        : "r"((a)[0]), "r"((a)[1]), "r"((a)[2]), "r"((a)[3]), \
          "r"((b)[0]), "r"((b)[1]))

#define LDMX4(r0, r1, r2, r3, addr) \
    asm volatile("ldmatrix.sync.aligned.m8n8.x4.shared.b16 {%0,%1,%2,%3}, [%4];" \
        : "=r"(r0), "=r"(r1), "=r"(r2), "=r"(r3) : "r"(addr))

// ========================= fp16 mma.sync GEMM ==============================
// CTA tile 128x128, K-tile 64, 8 warps (4m x 2n), warp tile 32x64.
// 3-stage cp.async pipeline -> 110.6 KB smem -> 2 CTAs/SM. K compile-time.
#define LDH_    72
#define ATILEH_ (128 * LDH_)               // halves
#define BTILEH_ (128 * LDH_)
#define STGB_   ((ATILEH_ + BTILEH_) * 2)  // 36864 bytes per stage
#define NSTG_   3
#define GSMEM_  (NSTG_ * STGB_)            // 110592 bytes

template <int K>
__device__ __forceinline__ void g_load_tile(const __half* __restrict__ A,
                                            const __half* __restrict__ Bt,
                                            int m0, int n0, int kt,
                                            uint32_t su, int stage, int tid) {
    const __half* Ag = A  + (size_t)m0 * K + kt * 64;
    const __half* Bg = Bt + (size_t)n0 * K + kt * 64;
    uint32_t as = su + stage * STGB_;
    uint32_t bs = as + ATILEH_ * 2;
#pragma unroll
    for (int i = 0; i < 4; i++) {
        int c = tid + (i << 8);
        int row = c >> 3, c8 = c & 7;
        CP_ASYNC16(as + row * (LDH_ * 2) + (c8 << 4),
                   Ag + (size_t)row * K + (c8 << 3));
    }
#pragma unroll
    for (int i = 0; i < 4; i++) {
        int c = tid + (i << 8);
        int row = c >> 3, c8 = c & 7;
        CP_ASYNC16(bs + row * (LDH_ * 2) + (c8 << 4),
                   Bg + (size_t)row * K + (c8 << 3));
    }
    CP_COMMIT();
}

#define GEMM_MAINLOOP(A_, B_ptr_, K_)                                            \
    constexpr int T = (K_) / 64;                                                 \
    const uint32_t a_loff = (wm + ((lane >> 3) & 1) * 8 + (lane & 7)) *          \
                            (LDH_ * 2) + (lane >> 4) * 16;                       \
    const uint32_t b_loff = ATILEH_ * 2 +                                        \
                            (wn + ((lane >> 4) & 1) * 8 + (lane & 7)) *          \
                            (LDH_ * 2) + ((lane >> 3) & 1) * 16;                 \
    g_load_tile<K_>(A_, B_ptr_, m0, n0, 0, su, 0, tid);                          \
    if (T > 1) g_load_tile<K_>(A_, B_ptr_, m0, n0, 1, su, 1, tid);               \
    _Pragma("unroll")                                                            \
    for (int kt = 0; kt < T; kt++) {                                             \
        if (kt + 2 <= T) CP_WAIT1(); else CP_WAIT0();                            \
        __syncthreads();                                                         \
        if (kt + 2 < T)                                                          \
            g_load_tile<K_>(A_, B_ptr_, m0, n0, kt + 2, su, (kt + 2) % NSTG_, tid); \
        uint32_t sbase = su + (kt % NSTG_) * STGB_;                              \
        _Pragma("unroll")                                                        \
        for (int kk = 0; kk < 4; kk++) {                                         \
            uint32_t a[2][4], b[8][2];                                           \
            uint32_t koff = kk * 32;                                             \
            _Pragma("unroll")                                                    \
            for (int mt = 0; mt < 2; mt++)                                       \
                LDMX4(a[mt][0], a[mt][1], a[mt][2], a[mt][3],                    \
                      sbase + a_loff + koff + mt * (16 * LDH_ * 2));             \
            _Pragma("unroll")                                                    \
            for (int p = 0; p < 4; p++)                                          \
                LDMX4(b[2 * p][0], b[2 * p][1], b[2 * p + 1][0], b[2 * p + 1][1],\
                      sbase + b_loff + koff + p * (16 * LDH_ * 2));              \
            _Pragma("unroll")                                                    \
            for (int mt = 0; mt < 2; mt++)                                       \
                _Pragma("unroll")                                                \
                for (int nt = 0; nt < 8; nt++)                                   \
                    MMA_F16(acc[mt][nt], a[mt], b[nt]);                          \
        }                                                                        \
    }

// FFN1: gelu(x+bias) -> fp16 mid.  N = FFN_, K = D_.
__global__ __launch_bounds__(256, 2)
void ffn1_gemm(const __half* __restrict__ A, const __half* __restrict__ Bt,
               const float* __restrict__ bias, __half* __restrict__ Ch) {
    extern __shared__ float sm[];
    uint32_t su = smem_u32(sm);
    const int tid = threadIdx.x, lane = tid & 31, warp = tid >> 5;
    const int m0 = blockIdx.y * 128, n0 = blockIdx.x * 128;
    const int wm = (warp >> 1) * 32, wn = (warp & 1) * 64;
    const int lg = lane >> 2, l4 = lane & 3;
    constexpr int N = FFN_;

    float acc[2][8][4];
#pragma unroll
    for (int mt = 0; mt < 2; mt++)
#pragma unroll
        for (int nt = 0; nt < 8; nt++)
#pragma unroll
            for (int e = 0; e < 4; e++) acc[mt][nt][e] = 0.f;

    GEMM_MAINLOOP(A, Bt, D_)

#pragma unroll
    for (int mt = 0; mt < 2; mt++) {
#pragma unroll
        for (int nt = 0; nt < 8; nt++) {
            int row = m0 + wm + mt * 16 + lg;
            int col = n0 + wn + nt * 8 + l4 * 2;
            float b0 = __ldg(bias + col), b1 = __ldg(bias + col + 1);
#pragma unroll
            for (int half_ = 0; half_ < 2; half_++) {
                int r = row + half_ * 8;
                float v0 = acc[mt][nt][half_ * 2 + 0] + b0;
                float v1 = acc[mt][nt][half_ * 2 + 1] + b1;
                v0 = 0.5f * v0 * (1.0f + erff(v0 * 0.70710678118654752f));
                v1 = 0.5f * v1 * (1.0f + erff(v1 * 0.70710678118654752f));
                *(half2*)(Ch + (size_t)r * N + col) = __floats2half2_rn(v0, v1);
            }
        }
    }
}

// FFN2: h += x + bias.  N = D_, K = FFN_.
__global__ __launch_bounds__(256, 2)
void ffn2_gemm(const __half* __restrict__ A, const __half* __restrict__ Bt,
               const float* __restrict__ bias, float* __restrict__ C) {
    extern __shared__ float sm[];
    uint32_t su = smem_u32(sm);
    const int tid = threadIdx.x, lane = tid & 31, warp = tid >> 5;
    const int m0 = blockIdx.y * 128, n0 = blockIdx.x * 128;
    const int wm = (warp >> 1) * 32, wn = (warp & 1) * 64;
    const int lg = lane >> 2, l4 = lane & 3;
    constexpr int N = D_;

    float acc[2][8][4];
#pragma unroll
    for (int mt = 0; mt < 2; mt++)
#pragma unroll
        for (int nt = 0; nt < 8; nt++)
#pragma unroll
            for (int e = 0; e < 4; e++) acc[mt][nt][e] = 0.f;

    GEMM_MAINLOOP(A, Bt, FFN_)

#pragma unroll
    for (int mt = 0; mt < 2; mt++) {
#pragma unroll
        for (int nt = 0; nt < 8; nt++) {
            int row = m0 + wm + mt * 16 + lg;
            int col = n0 + wn + nt * 8 + l4 * 2;
            float b0 = __ldg(bias + col), b1 = __ldg(bias + col + 1);
#pragma unroll
            for (int half_ = 0; half_ < 2; half_++) {
                int r = row + half_ * 8;
                float2* p = (float2*)(C + (size_t)r * N + col);
                float2 o = *p;
                o.x += acc[mt][nt][half_ * 2 + 0] + b0;
                o.y += acc[mt][nt][half_ * 2 + 1] + b1;
                *p = o;
            }
        }
    }
}

// Fused QKV GEMM -> fp16 outputs; square epilogue for q,k.  N = K = D_.
__global__ __launch_bounds__(256, 2)
void qkv_gemm(const __half* __restrict__ A,
              const __half* __restrict__ WqT, const __half* __restrict__ WkT,
              const __half* __restrict__ WvT,
              const float* __restrict__ bq, const float* __restrict__ bk,
              const float* __restrict__ bv,
              __half* __restrict__ Q, __half* __restrict__ Ko, __half* __restrict__ V) {
    extern __shared__ float sm[];
    uint32_t su = smem_u32(sm);
    const int tid = threadIdx.x, lane = tid & 31, warp = tid >> 5;
    const int which = blockIdx.x >> 1;
    const int m0 = blockIdx.y * 128, n0 = (blockIdx.x & 1) * 128;
    const int wm = (warp >> 1) * 32, wn = (warp & 1) * 64;
    const int lg = lane >> 2, l4 = lane & 3;
    constexpr int N = D_;

    const __half* Bt  = (which == 0) ? WqT : (which == 1) ? WkT : WvT;
    const float* bias = (which == 0) ? bq : (which == 1) ? bk : bv;
    __half* C = (which == 0) ? Q : (which == 1) ? Ko : V;
    const bool sq = (which < 2);

    float acc[2][8][4];
#pragma unroll
    for (int mt = 0; mt < 2; mt++)
#pragma unroll
        for (int nt = 0; nt < 8; nt++)
#pragma unroll
            for (int e = 0; e < 4; e++) acc[mt][nt][e] = 0.f;

    GEMM_MAINLOOP(A, Bt, D_)

#pragma unroll
    for (int mt = 0; mt < 2; mt++) {
#pragma unroll
        for (int nt = 0; nt < 8; nt++) {
            int row = m0 + wm + mt * 16 + lg;
            int col = n0 + wn + nt * 8 + l4 * 2;
            float b0 = __ldg(bias + col), b1 = __ldg(bias + col + 1);
#pragma unroll
            for (int half_ = 0; half_ < 2; half_++) {
                int r = row + half_ * 8;
                float v0 = acc[mt][nt][half_ * 2 + 0] + b0;
                float v1 = acc[mt][nt][half_ * 2 + 1] + b1;
                if (sq) { v0 = v0 * v0; v1 = v1 * v1; }
                *(half2*)(C + (size_t)r * N + col) = __floats2half2_rn(v0, v1);
            }
        }
    }
}

// -------- weight transpose+convert: out[n*K+k] = fp16(in[k*N+n]) ------------
__global__ void transconv_kernel(const float* __restrict__ in, __half* __restrict__ out,
                                 int Kdim, int Ndim) {
    __shared__ float t[32][33];
    size_t off = (size_t)blockIdx.z * Kdim * Ndim;
    int k0 = blockIdx.y * 32, n0 = blockIdx.x * 32;
    int tx = threadIdx.x, ty = threadIdx.y;   // 32 x 8
#pragma unroll
    for (int i = ty; i < 32; i += 8)
        t[i][tx] = in[off + (size_t)(k0 + i) * Ndim + n0 + tx];
    __syncthreads();
#pragma unroll
    for (int i = ty; i < 32; i += 8)
        out[off + (size_t)(n0 + i) * Kdim + k0 + tx] = __float2half_rn(t[tx][i]);
}

// half8 -> 8 floats
__device__ __forceinline__ void h8_to_f8(uint4 raw, float* f) {
    half2* hp = (half2*)&raw;
#pragma unroll
    for (int i = 0; i < 4; i++) {
        float2 fv = __half22float2(hp[i]);
        f[2 * i] = fv.x; f[2 * i + 1] = fv.y;
    }
}

// ========= attention phase 1: per-chunk K^T V and sum(k) (fp16 in) =========
__global__ __launch_bounds__(256)
void attn_p1(const __half* __restrict__ k, const __half* __restrict__ v,
             float* __restrict__ ckv, float* __restrict__ cks) {
    __shared__ float Ks[CH_][36], Vs[CH_][36];
    int blk = blockIdx.x;
    int c = blk & (NC_ - 1);
    int bh = blk >> 5;
    int b = bh >> 3, hh = bh & 7;
    int t = threadIdx.x;
    size_t base = ((size_t)(b * G_ + c * CH_)) * D_ + hh * DH_;

    {
        int row = t >> 2, c8 = (t & 3) * 8;
        size_t gi = base + (size_t)row * D_ + c8;
        float kf[8], vf[8];
        h8_to_f8(*(const uint4*)(k + gi), kf);
        h8_to_f8(*(const uint4*)(v + gi), vf);
#pragma unroll
        for (int i = 0; i < 8; i++) { Ks[row][c8 + i] = kf[i]; Vs[row][c8 + i] = vf[i]; }
    }
    __syncthreads();

    int f = t >> 4, d0 = (t & 15) * 2;
    float a00 = 0.f, a01 = 0.f, a10 = 0.f, a11 = 0.f;
#pragma unroll
    for (int i = 0; i < CH_; i++) {
        float k0v = Ks[i][f];
        float k1v = Ks[i][f + 16];
        float2 vv = *(float2*)&Vs[i][d0];
        a00 = fmaf(k0v, vv.x, a00); a01 = fmaf(k0v, vv.y, a01);
        a10 = fmaf(k1v, vv.x, a10); a11 = fmaf(k1v, vv.y, a11);
    }
    float* cbase = ckv + (size_t)blk * (DH_ * DH_);
    *(float2*)(cbase + f * DH_ + d0)        = make_float2(a00, a01);
    *(float2*)(cbase + (f + 16) * DH_ + d0) = make_float2(a10, a11);

    if (t < DH_) {
        float s = 0.f;
#pragma unroll
        for (int i = 0; i < CH_; i++) s += Ks[i][t];
        cks[(size_t)blk * DH_ + t] = s;
    }
}

// ========= attention phase 2: exclusive prefix across chunks ===============
__global__ void attn_p2(float* __restrict__ ckv, float* __restrict__ cks) {
    int bh = blockIdx.x;
    int t = threadIdx.x;   // 1024 threads
    float run = 0.f;
    for (int c = 0; c < NC_; c++) {
        size_t idx = ((size_t)(bh * NC_ + c)) * (DH_ * DH_) + t;
        float tmp = ckv[idx];
        ckv[idx] = run;
        run += tmp;
    }
    if (t < DH_) {
        float r2 = 0.f;
        for (int c = 0; c < NC_; c++) {
            size_t idx = ((size_t)(bh * NC_ + c)) * DH_ + t;
            float tmp = cks[idx];
            cks[idx] = r2;
            r2 += tmp;
        }
    }
}

// ========= attention phase 3: output + residual, paired rows ===============
__global__ __launch_bounds__(256)
void attn_p3(const __half* __restrict__ q, const __half* __restrict__ k,
             const __half* __restrict__ v,
             const float* __restrict__ ckv, const float* __restrict__ cks,
             float* __restrict__ h) {
    __shared__ float Qs[CH_][36];
    __shared__ float Vs[CH_][36];
    __shared__ float Kt[DH_][68];
    __shared__ float As[CH_][66];
    __shared__ float Ss[DH_][36];
    __shared__ float den[CH_], zz[DH_];

    int blk = blockIdx.x;
    int c = blk & (NC_ - 1);
    int bh = blk >> 5;
    int b = bh >> 3, hh = bh & 7;
    int t = threadIdx.x;
    size_t base = ((size_t)(b * G_ + c * CH_)) * D_ + hh * DH_;

    {
        int row = t >> 2, c8 = (t & 3) * 8;
        size_t gi = base + (size_t)row * D_ + c8;
        float qf[8], kf[8], vf[8];
        h8_to_f8(*(const uint4*)(q + gi), qf);
        h8_to_f8(*(const uint4*)(k + gi), kf);
        h8_to_f8(*(const uint4*)(v + gi), vf);
#pragma unroll
        for (int i = 0; i < 8; i++) {
            Qs[row][c8 + i] = qf[i];
            Vs[row][c8 + i] = vf[i];
            Kt[c8 + i][row] = kf[i];
        }
    }
#pragma unroll
    for (int it = 0; it < 4; it++) {
        int e = t + it * 256;
        Ss[e >> 5][e & 31] = ckv[(size_t)blk * (DH_ * DH_) + e];
    }
    if (t < DH_) zz[t] = cks[(size_t)blk * DH_ + t];
    __syncthreads();

    {
        int i0 = (t >> 4) * 4, j0 = (t & 15) * 4;
        float a4[4][4];
#pragma unroll
        for (int r = 0; r < 4; r++)
#pragma unroll
            for (int cc = 0; cc < 4; cc++) a4[r][cc] = 0.f;
#pragma unroll
        for (int f = 0; f < DH_; f++) {
            float qr[4];
#pragma unroll
            for (int r = 0; r < 4; r++) qr[r] = Qs[i0 + r][f];
            float4 kk = *(float4*)&Kt[f][j0];
#pragma unroll
            for (int r = 0; r < 4; r++) {
                a4[r][0] = fmaf(qr[r], kk.x, a4[r][0]);
                a4[r][1] = fmaf(qr[r], kk.y, a4[r][1]);
                a4[r][2] = fmaf(qr[r], kk.z, a4[r][2]);
                a4[r][3] = fmaf(qr[r], kk.w, a4[r][3]);
            }
        }
#pragma unroll
        for (int r = 0; r < 4; r++)
#pragma unroll
            for (int cc = 0; cc < 4; cc++) As[i0 + r][j0 + cc] = a4[r][cc];
    }
    __syncthreads();

    {
        int i = t >> 2, r = t & 3;
        float s = 0.f;
        for (int f = r; f < DH_; f += 4) s = fmaf(Qs[i][f], zz[f], s);
        for (int j = r; j <= i; j += 4) s += As[i][j];
        s += __shfl_xor_sync(0xffffffffu, s, 1);
        s += __shfl_xor_sync(0xffffffffu, s, 2);
        if (r == 0) den[i] = s;
    }
    __syncthreads();

    {
        int i1 = t >> 3, i2 = i1 + 32;
        int d0 = (t & 7) * 4;
        float o10 = 0.f, o11 = 0.f, o12 = 0.f, o13 = 0.f;
        float o20 = 0.f, o21 = 0.f, o22 = 0.f, o23 = 0.f;
#pragma unroll
        for (int f = 0; f < DH_; f++) {
            float4 ss = *(float4*)&Ss[f][d0];
            float q1 = Qs[i1][f], q2 = Qs[i2][f];
            o10 = fmaf(q1, ss.x, o10); o11 = fmaf(q1, ss.y, o11);
            o12 = fmaf(q1, ss.z, o12); o13 = fmaf(q1, ss.w, o13);
            o20 = fmaf(q2, ss.x, o20); o21 = fmaf(q2, ss.y, o21);
            o22 = fmaf(q2, ss.z, o22); o23 = fmaf(q2, ss.w, o23);
        }
        for (int j = 0; j <= i1; j++) {
            float4 vv = *(float4*)&Vs[j][d0];
            float a1 = As[i1][j], a2 = As[i2][j];
            o10 = fmaf(a1, vv.x, o10); o11 = fmaf(a1, vv.y, o11);
            o12 = fmaf(a1, vv.z, o12); o13 = fmaf(a1, vv.w, o13);
            o20 = fmaf(a2, vv.x, o20); o21 = fmaf(a2, vv.y, o21);
            o22 = fmaf(a2, vv.z, o22); o23 = fmaf(a2, vv.w, o23);
        }
        for (int j = i1 + 1; j <= i2; j++) {
            float4 vv = *(float4*)&Vs[j][d0];
            float a2 = As[i2][j];
            o20 = fmaf(a2, vv.x, o20); o21 = fmaf(a2, vv.y, o21);
            o22 = fmaf(a2, vv.z, o22); o23 = fmaf(a2, vv.w, o23);
        }
        float inv1 = 1.0f / (den[i1] + 1e-16f);
        float inv2 = 1.0f / (den[i2] + 1e-16f);
        float4* p1 = (float4*)(h + base + (size_t)i1 * D_ + d0);
        float4 hv1 = *p1;
        hv1.x += o10 * inv1; hv1.y += o11 * inv1;
        hv1.z += o12 * inv1; hv1.w += o13 * inv1;
        *p1 = hv1;
        float4* p2 = (float4*)(h + base + (size_t)i2 * D_ + d0);
        float4 hv2 = *p2;
        hv2.x += o20 * inv2; hv2.y += o21 * inv2;
        hv2.z += o22 * inv2; hv2.w += o23 * inv2;
        *p2 = hv2;
    }
}

// ---------------- embedding: h = gene_emb + REE(x) -------------------------
__global__ void embed_kernel(const float* __restrict__ x,
                             const float* __restrict__ ge,
                             const float* __restrict__ invf,
                             float* __restrict__ h) {
    size_t idx = (size_t)blockIdx.x * 256 + threadIdx.x;
    int d = (int)(idx & (D_ - 1));
    size_t bg = idx >> 8;
    int g = (int)(bg & (G_ - 1));
    float xv = x[bg];
    float e;
    if (d < D_ / 2) e = sinf(xv * invf[d]);
    else            e = cosf(xv * invf[d - D_ / 2]);
    if (xv == -10.0f) e = 0.0f;
    h[idx] = ge[(size_t)g * D_ + d] + e;
}

// ---------------- layernorm -> fp16 (warp per row, D=256) -------------------
__global__ void ln_kernel(const float* __restrict__ x,
                          const float* __restrict__ gam,
                          const float* __restrict__ bet,
                          __half* __restrict__ out) {
    int warp = threadIdx.x >> 5, lane = threadIdx.x & 31;
    int row = blockIdx.x * 8 + warp;
    const float* xr = x + (size_t)row * D_;
    float vals[8];
    float s = 0.f;
#pragma unroll
    for (int i = 0; i < 8; i++) { vals[i] = xr[lane + i * 32]; s += vals[i]; }
#pragma unroll
    for (int o = 16; o; o >>= 1) s += __shfl_xor_sync(0xffffffffu, s, o);
    float mean = s * (1.0f / D_);
    float vs = 0.f;
#pragma unroll
    for (int i = 0; i < 8; i++) { float dlt = vals[i] - mean; vs += dlt * dlt; }
#pragma unroll
    for (int o = 16; o; o >>= 1) vs += __shfl_xor_sync(0xffffffffu, vs, o);
    float rstd = rsqrtf(vs * (1.0f / D_) + 1e-5f);
    __half* orow = out + (size_t)row * D_;
#pragma unroll
    for (int i = 0; i < 8; i++) {
        int c = lane + i * 32;
        orow[c] = __float2half_rn((vals[i] - mean) * rstd * gam[c] + bet[c]);
    }
}

// ---------------- final projection: out = h @ Wout + bout -------------------
__global__ void out_kernel(const float* __restrict__ h, const float* __restrict__ Wout,
                           const float* __restrict__ bout, float* __restrict__ out) {
    int warp = threadIdx.x >> 5, lane = threadIdx.x & 31;
    int row = blockIdx.x * 8 + warp;
    const float* hr = h + (size_t)row * D_;
    float s = 0.f;
#pragma unroll
    for (int i = 0; i < 8; i++) {
        int c = lane + i * 32;
        s = fmaf(hr[c], Wout[c], s);
    }
#pragma unroll
    for (int o = 16; o; o >>= 1) s += __shfl_xor_sync(0xffffffffu, s, o);
    if (lane == 0) out[row] = s + bout[0];
}

// ---------------------------------------------------------------------------
extern "C" void kernel_launch(void* const* d_in, const int* in_sizes, int n_in,
                              void* d_out, int out_size) {
    const float* x        = (const float*)d_in[0];
    const float* gene_emb = (const float*)d_in[1];
    const float* inv_freq = (const float*)d_in[2];
    const float* Wq       = (const float*)d_in[3];
    const float* bq       = (const float*)d_in[4];
    const float* Wk       = (const float*)d_in[5];
    const float* bk       = (const float*)d_in[6];
    const float* Wv       = (const float*)d_in[7];
    const float* bv       = (const float*)d_in[8];
    const float* ln1_g    = (const float*)d_in[9];
    const float* ln1_b    = (const float*)d_in[10];
    const float* ln2_g    = (const float*)d_in[11];
    const float* ln2_b    = (const float*)d_in[12];
    const float* WU       = (const float*)d_in[13];
    const float* bU       = (const float*)d_in[14];
    const float* WV       = (const float*)d_in[15];
    const float* bV       = (const float*)d_in[16];
    const float* Wout     = (const float*)d_in[17];
    const float* bout     = (const float*)d_in[18];
    float* out = (float*)d_out;

    float *h, *ckv, *cks;
    __half *hn, *q, *k, *v, *mid, *WqT, *WkT, *WvT, *WUT, *WVT;
    cudaGetSymbolAddress((void**)&h,   g_h);
    cudaGetSymbolAddress((void**)&hn,  g_hn);
    cudaGetSymbolAddress((void**)&q,   g_q);
    cudaGetSymbolAddress((void**)&k,   g_k);
    cudaGetSymbolAddress((void**)&v,   g_v);
    cudaGetSymbolAddress((void**)&mid, g_mid);
    cudaGetSymbolAddress((void**)&ckv, g_ckv);
    cudaGetSymbolAddress((void**)&cks, g_cks);
    cudaGetSymbolAddress((void**)&WqT, g_WqT);
    cudaGetSymbolAddress((void**)&WkT, g_WkT);
    cudaGetSymbolAddress((void**)&WvT, g_WvT);
    cudaGetSymbolAddress((void**)&WUT, g_WUT);
    cudaGetSymbolAddress((void**)&WVT, g_WVT);

    cudaFuncSetAttribute(qkv_gemm,  cudaFuncAttributeMaxDynamicSharedMemorySize, GSMEM_);
    cudaFuncSetAttribute(ffn1_gemm, cudaFuncAttributeMaxDynamicSharedMemorySize, GSMEM_);
    cudaFuncSetAttribute(ffn2_gemm, cudaFuncAttributeMaxDynamicSharedMemorySize, GSMEM_);

    // batched transpose+convert (one launch per weight tensor, grid.z = L)
    {
        dim3 tb(32, 8);
        transconv_kernel<<<dim3(D_ / 32, D_ / 32, L_), tb>>>(Wq, WqT, D_, D_);
        transconv_kernel<<<dim3(D_ / 32, D_ / 32, L_), tb>>>(Wk, WkT, D_, D_);
        transconv_kernel<<<dim3(D_ / 32, D_ / 32, L_), tb>>>(Wv, WvT, D_, D_);
        transconv_kernel<<<dim3(FFN_ / 32, D_ / 32, L_), tb>>>(WU, WUT, D_, FFN_);
        transconv_kernel<<<dim3(D_ / 32, FFN_ / 32, L_), tb>>>(WV, WVT, FFN_, D_);
    }

    embed_kernel<<<(BG_ * D_) / 256, 256>>>(x, gene_emb, inv_freq, h);

    for (int l = 0; l < L_; l++) {
        const size_t wOff  = (size_t)l * D_ * D_;
        const size_t bOff  = (size_t)l * D_;
        const size_t uOff  = (size_t)l * D_ * FFN_;
        const size_t ubOff = (size_t)l * FFN_;
        const size_t vOff  = (size_t)l * FFN_ * D_;

        ln_kernel<<<BG_ / 8, 256>>>(h, ln1_g + bOff, ln1_b + bOff, hn);

        qkv_gemm<<<dim3(6, BG_ / 128), 256, GSMEM_>>>(
            hn, WqT + wOff, WkT + wOff, WvT + wOff,
            bq + bOff, bk + bOff, bv + bOff, q, k, v);

        attn_p1<<<BH_ * NC_, 256>>>(k, v, ckv, cks);
        attn_p2<<<BH_, 1024>>>(ckv, cks);
        attn_p3<<<BH_ * NC_, 256>>>(q, k, v, ckv, cks, h);

        ln_kernel<<<BG_ / 8, 256>>>(h, ln2_g + bOff, ln2_b + bOff, hn);

        ffn1_gemm<<<dim3(FFN_ / 128, BG_ / 128), 256, GSMEM_>>>(hn, WUT + uOff, bU + ubOff, mid);
        ffn2_gemm<<<dim3(D_ / 128, BG_ / 128), 256, GSMEM_>>>(mid, WVT + vOff, bV + bOff, h);
    }

    out_kernel<<<BG_ / 8, 256>>>(h, Wout, bout, out);
}

// round 16
// speedup vs baseline: 1.0697x; 1.0020x over previous
#include <cuda_runtime.h>
#include <cuda_fp16.h>
#include <math.h>
#include <stdint.h>

#define B_   16
#define G_   2048
#define D_   256
#define H_   8
#define DH_  32
#define FFN_ 1024
#define L_   4
#define CH_  64
#define NC_  (G_ / CH_)           // 32 chunks
#define BG_  (B_ * G_)            // 32768 rows
#define BH_  (B_ * H_)            // 128

// ---------------- scratch (device globals; no runtime allocation) ----------
__device__ float  g_h[(size_t)BG_ * D_];
__device__ __half g_hn[(size_t)BG_ * D_];
__device__ __half g_q[(size_t)BG_ * D_];
__device__ __half g_k[(size_t)BG_ * D_];
__device__ __half g_v[(size_t)BG_ * D_];
__device__ __half g_mid[(size_t)BG_ * FFN_];
__device__ float  g_ckv[(size_t)BH_ * NC_ * DH_ * DH_];
__device__ float  g_cks[(size_t)BH_ * NC_ * DH_];
// fp16 [N,K] K-major transposed weights
__device__ __half g_WqT[(size_t)L_ * D_ * D_];
__device__ __half g_WkT[(size_t)L_ * D_ * D_];
__device__ __half g_WvT[(size_t)L_ * D_ * D_];
__device__ __half g_WUT[(size_t)L_ * D_ * FFN_];
__device__ __half g_WVT[(size_t)L_ * FFN_ * D_];

// ========================= helpers =========================================
__device__ __forceinline__ uint32_t smem_u32(const void* p) {
    uint32_t a;
    asm("{ .reg .u64 t; cvta.to.shared.u64 t, %1; cvt.u32.u64 %0, t; }" : "=r"(a) : "l"(p));
    return a;
}
#define CP_ASYNC16(dst, src) \
    asm volatile("cp.async.cg.shared.global [%0], [%1], 16;" :: "r"(dst), "l"(src))
#define CP_COMMIT() asm volatile("cp.async.commit_group;" ::: "memory")
#define CP_WAIT0()  asm volatile("cp.async.wait_group 0;" ::: "memory")
#define CP_WAIT1()  asm volatile("cp.async.wait_group 1;" ::: "memory")

#define MMA_F16(c, a, b) \
    asm volatile("mma.sync.aligned.m16n8k16.row.col.f32.f16.f16.f32 " \
        "{%0,%1,%2,%3}, {%4,%5,%6,%7}, {%8,%9}, {%0,%1,%2,%3};" \
        : "+f"((c)[0]), "+f"((c)[1]), "+f"((c)[2]), "+f"((c)[3]) \
        : "r"((a)[0]), "r"((a)[1]), "r"((a)[2]), "r"((a)[3]), \
          "r"((b)[0]), "r"((b)[1]))

#define LDMX4(r0, r1, r2, r3, addr) \
    asm volatile("ldmatrix.sync.aligned.m8n8.x4.shared.b16 {%0,%1,%2,%3}, [%4];" \
        : "=r"(r0), "=r"(r1), "=r"(r2), "=r"(r3) : "r"(addr))

// ========================= fp16 mma.sync GEMM ==============================
// CTA tile 128x128, K-tile 64, 8 warps (4m x 2n), warp tile 32x64.
// 3-stage cp.async pipeline -> 110.6 KB smem -> 2 CTAs/SM. K compile-time.
#define LDH_    72
#define ATILEH_ (128 * LDH_)               // halves
#define BTILEH_ (128 * LDH_)
#define STGB_   ((ATILEH_ + BTILEH_) * 2)  // 36864 bytes per stage
#define NSTG_   3
#define GSMEM_  (NSTG_ * STGB_)            // 110592 bytes

template <int K>
__device__ __forceinline__ void g_load_tile(const __half* __restrict__ A,
                                            const __half* __restrict__ Bt,
                                            int m0, int n0, int kt,
                                            uint32_t su, int stage, int tid) {
    const __half* Ag = A  + (size_t)m0 * K + kt * 64;
    const __half* Bg = Bt + (size_t)n0 * K + kt * 64;
    uint32_t as = su + stage * STGB_;
    uint32_t bs = as + ATILEH_ * 2;
#pragma unroll
    for (int i = 0; i < 4; i++) {
        int c = tid + (i << 8);
        int row = c >> 3, c8 = c & 7;
        CP_ASYNC16(as + row * (LDH_ * 2) + (c8 << 4),
                   Ag + (size_t)row * K + (c8 << 3));
    }
#pragma unroll
    for (int i = 0; i < 4; i++) {
        int c = tid + (i << 8);
        int row = c >> 3, c8 = c & 7;
        CP_ASYNC16(bs + row * (LDH_ * 2) + (c8 << 4),
                   Bg + (size_t)row * K + (c8 << 3));
    }
    CP_COMMIT();
}

#define GEMM_MAINLOOP(A_, B_ptr_, K_)                                            \
    constexpr int T = (K_) / 64;                                                 \
    const uint32_t a_loff = (wm + ((lane >> 3) & 1) * 8 + (lane & 7)) *          \
                            (LDH_ * 2) + (lane >> 4) * 16;                       \
    const uint32_t b_loff = ATILEH_ * 2 +                                        \
                            (wn + ((lane >> 4) & 1) * 8 + (lane & 7)) *          \
                            (LDH_ * 2) + ((lane >> 3) & 1) * 16;                 \
    g_load_tile<K_>(A_, B_ptr_, m0, n0, 0, su, 0, tid);                          \
    if (T > 1) g_load_tile<K_>(A_, B_ptr_, m0, n0, 1, su, 1, tid);               \
    _Pragma("unroll")                                                            \
    for (int kt = 0; kt < T; kt++) {                                             \
        if (kt + 2 <= T) CP_WAIT1(); else CP_WAIT0();                            \
        __syncthreads();                                                         \
        if (kt + 2 < T)                                                          \
            g_load_tile<K_>(A_, B_ptr_, m0, n0, kt + 2, su, (kt + 2) % NSTG_, tid); \
        uint32_t sbase = su + (kt % NSTG_) * STGB_;                              \
        _Pragma("unroll")                                                        \
        for (int kk = 0; kk < 4; kk++) {                                         \
            uint32_t a[2][4], b[8][2];                                           \
            uint32_t koff = kk * 32;                                             \
            _Pragma("unroll")                                                    \
            for (int mt = 0; mt < 2; mt++)                                       \
                LDMX4(a[mt][0], a[mt][1], a[mt][2], a[mt][3],                    \
                      sbase + a_loff + koff + mt * (16 * LDH_ * 2));             \
            _Pragma("unroll")                                                    \
            for (int p = 0; p < 4; p++)                                          \
                LDMX4(b[2 * p][0], b[2 * p][1], b[2 * p + 1][0], b[2 * p + 1][1],\
                      sbase + b_loff + koff + p * (16 * LDH_ * 2));              \
            _Pragma("unroll")                                                    \
            for (int mt = 0; mt < 2; mt++)                                       \
                _Pragma("unroll")                                                \
                for (int nt = 0; nt < 8; nt++)                                   \
                    MMA_F16(acc[mt][nt], a[mt], b[nt]);                          \
        }                                                                        \
    }

// FFN1: gelu(x+bias) -> fp16 mid.  N = FFN_, K = D_.
__global__ __launch_bounds__(256, 2)
void ffn1_gemm(const __half* __restrict__ A, const __half* __restrict__ Bt,
               const float* __restrict__ bias, __half* __restrict__ Ch) {
    extern __shared__ float sm[];
    uint32_t su = smem_u32(sm);
    const int tid = threadIdx.x, lane = tid & 31, warp = tid >> 5;
    const int m0 = blockIdx.y * 128, n0 = blockIdx.x * 128;
    const int wm = (warp >> 1) * 32, wn = (warp & 1) * 64;
    const int lg = lane >> 2, l4 = lane & 3;
    constexpr int N = FFN_;

    float acc[2][8][4];
#pragma unroll
    for (int mt = 0; mt < 2; mt++)
#pragma unroll
        for (int nt = 0; nt < 8; nt++)
#pragma unroll
            for (int e = 0; e < 4; e++) acc[mt][nt][e] = 0.f;

    GEMM_MAINLOOP(A, Bt, D_)

#pragma unroll
    for (int mt = 0; mt < 2; mt++) {
#pragma unroll
        for (int nt = 0; nt < 8; nt++) {
            int row = m0 + wm + mt * 16 + lg;
            int col = n0 + wn + nt * 8 + l4 * 2;
            float b0 = __ldg(bias + col), b1 = __ldg(bias + col + 1);
#pragma unroll
            for (int half_ = 0; half_ < 2; half_++) {
                int r = row + half_ * 8;
                float v0 = acc[mt][nt][half_ * 2 + 0] + b0;
                float v1 = acc[mt][nt][half_ * 2 + 1] + b1;
                v0 = 0.5f * v0 * (1.0f + erff(v0 * 0.70710678118654752f));
                v1 = 0.5f * v1 * (1.0f + erff(v1 * 0.70710678118654752f));
                *(half2*)(Ch + (size_t)r * N + col) = __floats2half2_rn(v0, v1);
            }
        }
    }
}

// FFN2: h += x + bias.  N = D_, K = FFN_.
__global__ __launch_bounds__(256, 2)
void ffn2_gemm(const __half* __restrict__ A, const __half* __restrict__ Bt,
               const float* __restrict__ bias, float* __restrict__ C) {
    extern __shared__ float sm[];
    uint32_t su = smem_u32(sm);
    const int tid = threadIdx.x, lane = tid & 31, warp = tid >> 5;
    const int m0 = blockIdx.y * 128, n0 = blockIdx.x * 128;
    const int wm = (warp >> 1) * 32, wn = (warp & 1) * 64;
    const int lg = lane >> 2, l4 = lane & 3;
    constexpr int N = D_;

    float acc[2][8][4];
#pragma unroll
    for (int mt = 0; mt < 2; mt++)
#pragma unroll
        for (int nt = 0; nt < 8; nt++)
#pragma unroll
            for (int e = 0; e < 4; e++) acc[mt][nt][e] = 0.f;

    GEMM_MAINLOOP(A, Bt, FFN_)

#pragma unroll
    for (int mt = 0; mt < 2; mt++) {
#pragma unroll
        for (int nt = 0; nt < 8; nt++) {
            int row = m0 + wm + mt * 16 + lg;
            int col = n0 + wn + nt * 8 + l4 * 2;
            float b0 = __ldg(bias + col), b1 = __ldg(bias + col + 1);
#pragma unroll
            for (int half_ = 0; half_ < 2; half_++) {
                int r = row + half_ * 8;
                float2* p = (float2*)(C + (size_t)r * N + col);
                float2 o = *p;
                o.x += acc[mt][nt][half_ * 2 + 0] + b0;
                o.y += acc[mt][nt][half_ * 2 + 1] + b1;
                *p = o;
            }
        }
    }
}

// QKV GEMM -> fp16 outputs; square epilogue for q,k.  N = K = D_.
// which = which0 + (blockIdx.x>>1): 0=q, 1=k, 2=v.
__global__ __launch_bounds__(256, 2)
void qkv_gemm(const __half* __restrict__ A,
              const __half* __restrict__ WqT, const __half* __restrict__ WkT,
              const __half* __restrict__ WvT,
              const float* __restrict__ bq, const float* __restrict__ bk,
              const float* __restrict__ bv,
              __half* __restrict__ Q, __half* __restrict__ Ko, __half* __restrict__ V,
              int which0) {
    extern __shared__ float sm[];
    uint32_t su = smem_u32(sm);
    const int tid = threadIdx.x, lane = tid & 31, warp = tid >> 5;
    const int which = which0 + (blockIdx.x >> 1);
    const int m0 = blockIdx.y * 128, n0 = (blockIdx.x & 1) * 128;
    const int wm = (warp >> 1) * 32, wn = (warp & 1) * 64;
    const int lg = lane >> 2, l4 = lane & 3;
    constexpr int N = D_;

    const __half* Bt  = (which == 0) ? WqT : (which == 1) ? WkT : WvT;
    const float* bias = (which == 0) ? bq : (which == 1) ? bk : bv;
    __half* C = (which == 0) ? Q : (which == 1) ? Ko : V;
    const bool sq = (which < 2);

    float acc[2][8][4];
#pragma unroll
    for (int mt = 0; mt < 2; mt++)
#pragma unroll
        for (int nt = 0; nt < 8; nt++)
#pragma unroll
            for (int e = 0; e < 4; e++) acc[mt][nt][e] = 0.f;

    GEMM_MAINLOOP(A, Bt, D_)

#pragma unroll
    for (int mt = 0; mt < 2; mt++) {
#pragma unroll
        for (int nt = 0; nt < 8; nt++) {
            int row = m0 + wm + mt * 16 + lg;
            int col = n0 + wn + nt * 8 + l4 * 2;
            float b0 = __ldg(bias + col), b1 = __ldg(bias + col + 1);
#pragma unroll
            for (int half_ = 0; half_ < 2; half_++) {
                int r = row + half_ * 8;
                float v0 = acc[mt][nt][half_ * 2 + 0] + b0;
                float v1 = acc[mt][nt][half_ * 2 + 1] + b1;
                if (sq) { v0 = v0 * v0; v1 = v1 * v1; }
                *(half2*)(C + (size_t)r * N + col) = __floats2half2_rn(v0, v1);
            }
        }
    }
}

// -------- weight transpose+convert: out[n*K+k] = fp16(in[k*N+n]) ------------
__global__ void transconv_kernel(const float* __restrict__ in, __half* __restrict__ out,
                                 int Kdim, int Ndim) {
    __shared__ float t[32][33];
    size_t off = (size_t)blockIdx.z * Kdim * Ndim;
    int k0 = blockIdx.y * 32, n0 = blockIdx.x * 32;
    int tx = threadIdx.x, ty = threadIdx.y;   // 32 x 8
#pragma unroll
    for (int i = ty; i < 32; i += 8)
        t[i][tx] = in[off + (size_t)(k0 + i) * Ndim + n0 + tx];
    __syncthreads();
#pragma unroll
    for (int i = ty; i < 32; i += 8)
        out[off + (size_t)(n0 + i) * Kdim + k0 + tx] = __float2half_rn(t[tx][i]);
}

// half8 -> 8 floats
__device__ __forceinline__ void h8_to_f8(uint4 raw, float* f) {
    half2* hp = (half2*)&raw;
#pragma unroll
    for (int i = 0; i < 4; i++) {
        float2 fv = __half22float2(hp[i]);
        f[2 * i] = fv.x; f[2 * i + 1] = fv.y;
    }
}

// ========= attention phase 1: per-chunk K^T V and sum(k) (fp16 in) =========
__global__ __launch_bounds__(256)
void attn_p1(const __half* __restrict__ k, const __half* __restrict__ v,
             float* __restrict__ ckv, float* __restrict__ cks) {
    __shared__ float Ks[CH_][36], Vs[CH_][36];
    int blk = blockIdx.x;
    int c = blk & (NC_ - 1);
    int bh = blk >> 5;
    int b = bh >> 3, hh = bh & 7;
    int t = threadIdx.x;
    size_t base = ((size_t)(b * G_ + c * CH_)) * D_ + hh * DH_;

    {
        int row = t >> 2, c8 = (t & 3) * 8;
        size_t gi = base + (size_t)row * D_ + c8;
        float kf[8], vf[8];
        h8_to_f8(*(const uint4*)(k + gi), kf);
        h8_to_f8(*(const uint4*)(v + gi), vf);
#pragma unroll
        for (int i = 0; i < 8; i++) { Ks[row][c8 + i] = kf[i]; Vs[row][c8 + i] = vf[i]; }
    }
    __syncthreads();

    int f = t >> 4, d0 = (t & 15) * 2;
    float a00 = 0.f, a01 = 0.f, a10 = 0.f, a11 = 0.f;
#pragma unroll
    for (int i = 0; i < CH_; i++) {
        float k0v = Ks[i][f];
        float k1v = Ks[i][f + 16];
        float2 vv = *(float2*)&Vs[i][d0];
        a00 = fmaf(k0v, vv.x, a00); a01 = fmaf(k0v, vv.y, a01);
        a10 = fmaf(k1v, vv.x, a10); a11 = fmaf(k1v, vv.y, a11);
    }
    float* cbase = ckv + (size_t)blk * (DH_ * DH_);
    *(float2*)(cbase + f * DH_ + d0)        = make_float2(a00, a01);
    *(float2*)(cbase + (f + 16) * DH_ + d0) = make_float2(a10, a11);

    if (t < DH_) {
        float s = 0.f;
#pragma unroll
        for (int i = 0; i < CH_; i++) s += Ks[i][t];
        cks[(size_t)blk * DH_ + t] = s;
    }
}

// ========= attention phase 2: exclusive prefix across chunks ===============
__global__ void attn_p2(float* __restrict__ ckv, float* __restrict__ cks) {
    int bh = blockIdx.x;
    int t = threadIdx.x;   // 1024 threads
    float run = 0.f;
    for (int c = 0; c < NC_; c++) {
        size_t idx = ((size_t)(bh * NC_ + c)) * (DH_ * DH_) + t;
        float tmp = ckv[idx];
        ckv[idx] = run;
        run += tmp;
    }
    if (t < DH_) {
        float r2 = 0.f;
        for (int c = 0; c < NC_; c++) {
            size_t idx = ((size_t)(bh * NC_ + c)) * DH_ + t;
            float tmp = cks[idx];
            cks[idx] = r2;
            r2 += tmp;
        }
    }
}

// ========= attention phase 3: output + residual, paired rows ===============
__global__ __launch_bounds__(256)
void attn_p3(const __half* __restrict__ q, const __half* __restrict__ k,
             const __half* __restrict__ v,
             const float* __restrict__ ckv, const float* __restrict__ cks,
             float* __restrict__ h) {
    __shared__ float Qs[CH_][36];
    __shared__ float Vs[CH_][36];
    __shared__ float Kt[DH_][68];
    __shared__ float As[CH_][66];
    __shared__ float Ss[DH_][36];
    __shared__ float den[CH_], zz[DH_];

    int blk = blockIdx.x;
    int c = blk & (NC_ - 1);
    int bh = blk >> 5;
    int b = bh >> 3, hh = bh & 7;
    int t = threadIdx.x;
    size_t base = ((size_t)(b * G_ + c * CH_)) * D_ + hh * DH_;

    {
        int row = t >> 2, c8 = (t & 3) * 8;
        size_t gi = base + (size_t)row * D_ + c8;
        float qf[8], kf[8], vf[8];
        h8_to_f8(*(const uint4*)(q + gi), qf);
        h8_to_f8(*(const uint4*)(k + gi), kf);
        h8_to_f8(*(const uint4*)(v + gi), vf);
#pragma unroll
        for (int i = 0; i < 8; i++) {
            Qs[row][c8 + i] = qf[i];
            Vs[row][c8 + i] = vf[i];
            Kt[c8 + i][row] = kf[i];
        }
    }
#pragma unroll
    for (int it = 0; it < 4; it++) {
        int e = t + it * 256;
        Ss[e >> 5][e & 31] = ckv[(size_t)blk * (DH_ * DH_) + e];
    }
    if (t < DH_) zz[t] = cks[(size_t)blk * DH_ + t];
    __syncthreads();

    {
        int i0 = (t >> 4) * 4, j0 = (t & 15) * 4;
        float a4[4][4];
#pragma unroll
        for (int r = 0; r < 4; r++)
#pragma unroll
            for (int cc = 0; cc < 4; cc++) a4[r][cc] = 0.f;
#pragma unroll
        for (int f = 0; f < DH_; f++) {
            float qr[4];
#pragma unroll
            for (int r = 0; r < 4; r++) qr[r] = Qs[i0 + r][f];
            float4 kk = *(float4*)&Kt[f][j0];
#pragma unroll
            for (int r = 0; r < 4; r++) {
                a4[r][0] = fmaf(qr[r], kk.x, a4[r][0]);
                a4[r][1] = fmaf(qr[r], kk.y, a4[r][1]);
                a4[r][2] = fmaf(qr[r], kk.z, a4[r][2]);
                a4[r][3] = fmaf(qr[r], kk.w, a4[r][3]);
            }
        }
#pragma unroll
        for (int r = 0; r < 4; r++)
#pragma unroll
            for (int cc = 0; cc < 4; cc++) As[i0 + r][j0 + cc] = a4[r][cc];
    }
    __syncthreads();

    {
        int i = t >> 2, r = t & 3;
        float s = 0.f;
        for (int f = r; f < DH_; f += 4) s = fmaf(Qs[i][f], zz[f], s);
        for (int j = r; j <= i; j += 4) s += As[i][j];
        s += __shfl_xor_sync(0xffffffffu, s, 1);
        s += __shfl_xor_sync(0xffffffffu, s, 2);
        if (r == 0) den[i] = s;
    }
    __syncthreads();

    {
        int i1 = t >> 3, i2 = i1 + 32;
        int d0 = (t & 7) * 4;
        float o10 = 0.f, o11 = 0.f, o12 = 0.f, o13 = 0.f;
        float o20 = 0.f, o21 = 0.f, o22 = 0.f, o23 = 0.f;
#pragma unroll
        for (int f = 0; f < DH_; f++) {
            float4 ss = *(float4*)&Ss[f][d0];
            float q1 = Qs[i1][f], q2 = Qs[i2][f];
            o10 = fmaf(q1, ss.x, o10); o11 = fmaf(q1, ss.y, o11);
            o12 = fmaf(q1, ss.z, o12); o13 = fmaf(q1, ss.w, o13);
            o20 = fmaf(q2, ss.x, o20); o21 = fmaf(q2, ss.y, o21);
            o22 = fmaf(q2, ss.z, o22); o23 = fmaf(q2, ss.w, o23);
        }
        for (int j = 0; j <= i1; j++) {
            float4 vv = *(float4*)&Vs[j][d0];
            float a1 = As[i1][j], a2 = As[i2][j];
            o10 = fmaf(a1, vv.x, o10); o11 = fmaf(a1, vv.y, o11);
            o12 = fmaf(a1, vv.z, o12); o13 = fmaf(a1, vv.w, o13);
            o20 = fmaf(a2, vv.x, o20); o21 = fmaf(a2, vv.y, o21);
            o22 = fmaf(a2, vv.z, o22); o23 = fmaf(a2, vv.w, o23);
        }
        for (int j = i1 + 1; j <= i2; j++) {
            float4 vv = *(float4*)&Vs[j][d0];
            float a2 = As[i2][j];
            o20 = fmaf(a2, vv.x, o20); o21 = fmaf(a2, vv.y, o21);
            o22 = fmaf(a2, vv.z, o22); o23 = fmaf(a2, vv.w, o23);
        }
        float inv1 = 1.0f / (den[i1] + 1e-16f);
        float inv2 = 1.0f / (den[i2] + 1e-16f);
        float4* p1 = (float4*)(h + base + (size_t)i1 * D_ + d0);
        float4 hv1 = *p1;
        hv1.x += o10 * inv1; hv1.y += o11 * inv1;
        hv1.z += o12 * inv1; hv1.w += o13 * inv1;
        *p1 = hv1;
        float4* p2 = (float4*)(h + base + (size_t)i2 * D_ + d0);
        float4 hv2 = *p2;
        hv2.x += o20 * inv2; hv2.y += o21 * inv2;
        hv2.z += o22 * inv2; hv2.w += o23 * inv2;
        *p2 = hv2;
    }
}

// ---------------- embedding: h = gene_emb + REE(x) -------------------------
__global__ void embed_kernel(const float* __restrict__ x,
                             const float* __restrict__ ge,
                             const float* __restrict__ invf,
                             float* __restrict__ h) {
    size_t idx = (size_t)blockIdx.x * 256 + threadIdx.x;
    int d = (int)(idx & (D_ - 1));
    size_t bg = idx >> 8;
    int g = (int)(bg & (G_ - 1));
    float xv = x[bg];
    float e;
    if (d < D_ / 2) e = sinf(xv * invf[d]);
    else            e = cosf(xv * invf[d - D_ / 2]);
    if (xv == -10.0f) e = 0.0f;
    h[idx] = ge[(size_t)g * D_ + d] + e;
}

// ---------------- layernorm -> fp16 (warp per row, vectorized) --------------
__global__ void ln_kernel(const float* __restrict__ x,
                          const float* __restrict__ gam,
                          const float* __restrict__ bet,
                          __half* __restrict__ out) {
    int warp = threadIdx.x >> 5, lane = threadIdx.x & 31;
    int row = blockIdx.x * 8 + warp;
    const float4* xr = (const float4*)(x + (size_t)row * D_);
    float4 v0 = xr[lane], v1 = xr[lane + 32];
    float s = v0.x + v0.y + v0.z + v0.w + v1.x + v1.y + v1.z + v1.w;
#pragma unroll
    for (int o = 16; o; o >>= 1) s += __shfl_xor_sync(0xffffffffu, s, o);
    float mean = s * (1.0f / D_);
    float vs = 0.f;
    {
        float d;
        d = v0.x - mean; vs += d * d; d = v0.y - mean; vs += d * d;
        d = v0.z - mean; vs += d * d; d = v0.w - mean; vs += d * d;
        d = v1.x - mean; vs += d * d; d = v1.y - mean; vs += d * d;
        d = v1.z - mean; vs += d * d; d = v1.w - mean; vs += d * d;
    }
#pragma unroll
    for (int o = 16; o; o >>= 1) vs += __shfl_xor_sync(0xffffffffu, vs, o);
    float rstd = rsqrtf(vs * (1.0f / D_) + 1e-5f);

    const float4* gp = (const float4*)gam;
    const float4* bp = (const float4*)bet;
    float4 g0 = gp[lane], g1 = gp[lane + 32];
    float4 b0 = bp[lane], b1 = bp[lane + 32];
    half2 o0 = __floats2half2_rn((v0.x - mean) * rstd * g0.x + b0.x,
                                 (v0.y - mean) * rstd * g0.y + b0.y);
    half2 o1 = __floats2half2_rn((v0.z - mean) * rstd * g0.z + b0.z,
                                 (v0.w - mean) * rstd * g0.w + b0.w);
    half2 o2 = __floats2half2_rn((v1.x - mean) * rstd * g1.x + b1.x,
                                 (v1.y - mean) * rstd * g1.y + b1.y);
    half2 o3 = __floats2half2_rn((v1.z - mean) * rstd * g1.z + b1.z,
                                 (v1.w - mean) * rstd * g1.w + b1.w);
    uint2* orow = (uint2*)(out + (size_t)row * D_);
    uint2 w0, w1;
    w0.x = *(uint32_t*)&o0; w0.y = *(uint32_t*)&o1;
    w1.x = *(uint32_t*)&o2; w1.y = *(uint32_t*)&o3;
    orow[lane] = w0;
    orow[lane + 32] = w1;
}

// ---------------- final projection: out = h @ Wout + bout -------------------
__global__ void out_kernel(const float* __restrict__ h, const float* __restrict__ Wout,
                           const float* __restrict__ bout, float* __restrict__ out) {
    int warp = threadIdx.x >> 5, lane = threadIdx.x & 31;
    int row = blockIdx.x * 8 + warp;
    const float* hr = h + (size_t)row * D_;
    float s = 0.f;
#pragma unroll
    for (int i = 0; i < 8; i++) {
        int c = lane + i * 32;
        s = fmaf(hr[c], Wout[c], s);
    }
#pragma unroll
    for (int o = 16; o; o >>= 1) s += __shfl_xor_sync(0xffffffffu, s, o);
    if (lane == 0) out[row] = s + bout[0];
}

// ---------------------------------------------------------------------------
extern "C" void kernel_launch(void* const* d_in, const int* in_sizes, int n_in,
                              void* d_out, int out_size) {
    const float* x        = (const float*)d_in[0];
    const float* gene_emb = (const float*)d_in[1];
    const float* inv_freq = (const float*)d_in[2];
    const float* Wq       = (const float*)d_in[3];
    const float* bq       = (const float*)d_in[4];
    const float* Wk       = (const float*)d_in[5];
    const float* bk       = (const float*)d_in[6];
    const float* Wv       = (const float*)d_in[7];
    const float* bv       = (const float*)d_in[8];
    const float* ln1_g    = (const float*)d_in[9];
    const float* ln1_b    = (const float*)d_in[10];
    const float* ln2_g    = (const float*)d_in[11];
    const float* ln2_b    = (const float*)d_in[12];
    const float* WU       = (const float*)d_in[13];
    const float* bU       = (const float*)d_in[14];
    const float* WV       = (const float*)d_in[15];
    const float* bV       = (const float*)d_in[16];
    const float* Wout     = (const float*)d_in[17];
    const float* bout     = (const float*)d_in[18];
    float* out = (float*)d_out;

    float *h, *ckv, *cks;
    __half *hn, *q, *k, *v, *mid, *WqT, *WkT, *WvT, *WUT, *WVT;
    cudaGetSymbolAddress((void**)&h,   g_h);
    cudaGetSymbolAddress((void**)&hn,  g_hn);
    cudaGetSymbolAddress((void**)&q,   g_q);
    cudaGetSymbolAddress((void**)&k,   g_k);
    cudaGetSymbolAddress((void**)&v,   g_v);
    cudaGetSymbolAddress((void**)&mid, g_mid);
    cudaGetSymbolAddress((void**)&ckv, g_ckv);
    cudaGetSymbolAddress((void**)&cks, g_cks);
    cudaGetSymbolAddress((void**)&WqT, g_WqT);
    cudaGetSymbolAddress((void**)&WkT, g_WkT);
    cudaGetSymbolAddress((void**)&WvT, g_WvT);
    cudaGetSymbolAddress((void**)&WUT, g_WUT);
    cudaGetSymbolAddress((void**)&WVT, g_WVT);

    cudaFuncSetAttribute(qkv_gemm,  cudaFuncAttributeMaxDynamicSharedMemorySize, GSMEM_);
    cudaFuncSetAttribute(ffn1_gemm, cudaFuncAttributeMaxDynamicSharedMemorySize, GSMEM_);
    cudaFuncSetAttribute(ffn2_gemm, cudaFuncAttributeMaxDynamicSharedMemorySize, GSMEM_);

    // lazily-created secondary stream + fork/join events (first call is the
    // uncaptured correctness run; subsequent captured calls reuse them)
    static cudaStream_t s2 = nullptr;
    static cudaEvent_t evF = nullptr, evJ = nullptr;
    if (s2 == nullptr) {
        cudaStreamCreateWithFlags(&s2, cudaStreamNonBlocking);
        cudaEventCreateWithFlags(&evF, cudaEventDisableTiming);
        cudaEventCreateWithFlags(&evJ, cudaEventDisableTiming);
    }

    // transposes on stream 0, embed on s2 (independent)
    cudaEventRecord(evF, 0);
    cudaStreamWaitEvent(s2, evF, 0);
    embed_kernel<<<(BG_ * D_) / 256, 256, 0, s2>>>(x, gene_emb, inv_freq, h);
    cudaEventRecord(evJ, s2);
    {
        dim3 tb(32, 8);
        transconv_kernel<<<dim3(D_ / 32, D_ / 32, L_), tb>>>(Wq, WqT, D_, D_);
        transconv_kernel<<<dim3(D_ / 32, D_ / 32, L_), tb>>>(Wk, WkT, D_, D_);
        transconv_kernel<<<dim3(D_ / 32, D_ / 32, L_), tb>>>(Wv, WvT, D_, D_);
        transconv_kernel<<<dim3(FFN_ / 32, D_ / 32, L_), tb>>>(WU, WUT, D_, FFN_);
        transconv_kernel<<<dim3(D_ / 32, FFN_ / 32, L_), tb>>>(WV, WVT, FFN_, D_);
    }
    cudaStreamWaitEvent(0, evJ, 0);

    for (int l = 0; l < L_; l++) {
        const size_t wOff  = (size_t)l * D_ * D_;
        const size_t bOff  = (size_t)l * D_;
        const size_t uOff  = (size_t)l * D_ * FFN_;
        const size_t ubOff = (size_t)l * FFN_;
        const size_t vOff  = (size_t)l * FFN_ * D_;

        ln_kernel<<<BG_ / 8, 256>>>(h, ln1_g + bOff, ln1_b + bOff, hn);

        // fork: Q projection on s2, KV + attn_p1/p2 on stream 0
        cudaEventRecord(evF, 0);
        cudaStreamWaitEvent(s2, evF, 0);
        qkv_gemm<<<dim3(2, BG_ / 128), 256, GSMEM_, s2>>>(
            hn, WqT + wOff, WkT + wOff, WvT + wOff,
            bq + bOff, bk + bOff, bv + bOff, q, k, v, 0);
        cudaEventRecord(evJ, s2);

        qkv_gemm<<<dim3(4, BG_ / 128), 256, GSMEM_>>>(
            hn, WqT + wOff, WkT + wOff, WvT + wOff,
            bq + bOff, bk + bOff, bv + bOff, q, k, v, 1);
        attn_p1<<<BH_ * NC_, 256>>>(k, v, ckv, cks);
        attn_p2<<<BH_, 1024>>>(ckv, cks);

        cudaStreamWaitEvent(0, evJ, 0);   // join: q ready
        attn_p3<<<BH_ * NC_, 256>>>(q, k, v, ckv, cks, h);

        ln_kernel<<<BG_ / 8, 256>>>(h, ln2_g + bOff, ln2_b + bOff, hn);

        ffn1_gemm<<<dim3(FFN_ / 128, BG_ / 128), 256, GSMEM_>>>(hn, WUT + uOff, bU + ubOff, mid);
        ffn2_gemm<<<dim3(D_ / 128, BG_ / 128), 256, GSMEM_>>>(mid, WVT + vOff, bV + bOff, h);
    }

    out_kernel<<<BG_ / 8, 256>>>(h, Wout, bout, out);
}